// round 9
// baseline (speedup 1.0000x reference)
#include <cuda_runtime.h>
#include <cstdint>

// SubjectLayer: 256 SGEMMs (M=256,K=256,N=3000), tf32 mma.sync m16n8k8.
// R9: B tile stored transposed [n][k] in smem; B fragments via ldmatrix.x4
// (4 LDSM replace 16 LDS.32 per k8-step). A fragment-ordered tf32 scratch
// (R8). Raw-f32 B operand (tf32 HW truncation). Double-buffered kk frags.

#define NSP 3000
#define CIN 256
#define NSUBJ 128
#define TM 128
#define TN 128
#define TK 32
#define NCHUNK 8

#define A_WORDS 4096                   // 128x32 tf32 fragment-ordered per buffer
#define BT_STRIDE 36                   // words per n-row (144B, 16B aligned)
#define BT_WORDS (TN * BT_STRIDE)      // 4608
#define SMEM_WORDS (2 * (A_WORDS + BT_WORDS))
#define SMEM_BYTES (SMEM_WORDS * 4)    // 69632

// Fragment-ordered weights: [s][c(8)][mt(16)][kk(4)][lane(32)][r(4)]
__device__ uint32_t g_wfrag[NSUBJ * CIN * CIN];

__device__ __forceinline__ uint32_t f2tf32(float f) {
    uint32_t r;
    asm("cvt.rna.tf32.f32 %0, %1;" : "=r"(r) : "f"(f));
    return r;
}
__device__ __forceinline__ void cp16(uint32_t dst, const void* src) {
    asm volatile("cp.async.cg.shared.global [%0], [%1], 16;\n" :: "r"(dst), "l"(src));
}
__device__ __forceinline__ void cp4z(uint32_t dst, const void* src, int src_size) {
    asm volatile("cp.async.ca.shared.global [%0], [%1], 4, %2;\n"
                 :: "r"(dst), "l"(src), "r"(src_size));
}
__device__ __forceinline__ void ldsm4(uint32_t& r0, uint32_t& r1,
                                      uint32_t& r2, uint32_t& r3, uint32_t addr) {
    asm volatile("ldmatrix.sync.aligned.m8n8.x4.shared.b16 {%0,%1,%2,%3}, [%4];"
                 : "=r"(r0), "=r"(r1), "=r"(r2), "=r"(r3) : "r"(addr));
}
__device__ __forceinline__ void mma_tf32(float* d, const uint4 a,
                                         uint32_t b0, uint32_t b1) {
    asm volatile(
        "mma.sync.aligned.m16n8k8.row.col.f32.tf32.tf32.f32 "
        "{%0,%1,%2,%3}, {%4,%5,%6,%7}, {%8,%9}, {%0,%1,%2,%3};\n"
        : "+f"(d[0]), "+f"(d[1]), "+f"(d[2]), "+f"(d[3])
        : "r"(a.x), "r"(a.y), "r"(a.z), "r"(a.w), "r"(b0), "r"(b1));
}

// ---- Prologue: weights f32 -> tf32 fragment order ----
__global__ __launch_bounds__(256)
void wfrag_kernel(const float* __restrict__ w) {
    const int idx  = blockIdx.x * 256 + threadIdx.x;
    const int lane = idx & 31;
    const int kk   = (idx >> 5) & 3;
    const int mt   = (idx >> 7) & 15;
    const int c    = (idx >> 11) & 7;
    const int s    = idx >> 14;
    const int g = lane >> 2, t = lane & 3;
    const int m = mt * 16 + g;
    const int k = c * 32 + kk * 8 + t;
    const float* ws = w + (size_t)s * CIN * CIN;
    uint4 r;
    r.x = f2tf32(ws[(size_t)m       * CIN + k]);
    r.y = f2tf32(ws[(size_t)(m + 8) * CIN + k]);
    r.z = f2tf32(ws[(size_t)m       * CIN + k + 4]);
    r.w = f2tf32(ws[(size_t)(m + 8) * CIN + k + 4]);
    *reinterpret_cast<uint4*>(g_wfrag + (size_t)idx * 4) = r;
}

// ---- Main GEMM ----
extern __shared__ uint32_t smem[];

__global__ __launch_bounds__(256, 2)
void subject_tf32_kernel(const float* __restrict__ x,
                         const float* __restrict__ bias,
                         const int* __restrict__ subj,
                         float* __restrict__ out)
{
    const int b  = blockIdx.z;
    const int m0 = blockIdx.y * TM;
    const int n0 = blockIdx.x * TN;

    const int s = subj[b];
    const float* __restrict__ X  = x    + (size_t)b * CIN * NSP;
    const float* __restrict__ Bv = bias + (size_t)s * CIN;
    float* __restrict__ O        = out  + (size_t)b * CIN * NSP;

    const size_t wbase = ((size_t)s * 8) * 16 + (m0 >> 4);

    uint32_t* As = smem;                       // [2][4096] A fragments
    const uint32_t as_u32 = (uint32_t)__cvta_generic_to_shared(As);
    const uint32_t bt_u32 = as_u32 + 2 * A_WORDS * 4;   // [2][128][36] B^T

    const int tid    = threadIdx.x;
    const int wid    = tid >> 5;
    const int lane   = tid & 31;
    const int warp_m = wid & 3;
    const int warp_n = wid >> 2;
    const int group  = lane >> 2;
    const int tig    = lane & 3;
    const int bn     = warp_n * 64;

    float acc[2][8][4];
    #pragma unroll
    for (int mi = 0; mi < 2; mi++)
        #pragma unroll
        for (int ni = 0; ni < 8; ni++)
            #pragma unroll
            for (int r = 0; r < 4; r++)
                acc[mi][ni][r] = 0.0f;

    // B load coords: thread -> one n column, 16 k's (4B transposing cp.async)
    const int ln = tid & 127;
    const int kh = (tid >> 7) << 4;            // 0 or 16
    const int gn = n0 + ln;
    const int b_ok = (gn < NSP);

    auto load_chunk = [&](int buf, int c) {
        // A: contiguous 16KB fragment block
        const uint32_t* srcA = g_wfrag + (wbase + (size_t)c * 16) * 512;
        uint32_t abase = as_u32 + (uint32_t)buf * A_WORDS * 4;
        #pragma unroll
        for (int j = 0; j < 4; j++) {
            int u = j * 256 + tid;
            cp16(abase + (uint32_t)u * 16, srcA + (size_t)u * 4);
        }
        // B^T: BT[ln][kh+i] = X[k0+kh+i][gn]
        uint32_t bbase = bt_u32 + (uint32_t)buf * BT_WORDS * 4
                       + (uint32_t)(ln * BT_STRIDE + kh) * 4;
        const float* src = X + (size_t)(c * TK + kh) * NSP + (b_ok ? gn : 0);
        #pragma unroll
        for (int i = 0; i < 16; i++) {
            cp4z(bbase + (uint32_t)i * 4, src + (size_t)i * NSP, b_ok ? 4 : 0);
        }
        asm volatile("cp.async.commit_group;\n");
    };

    // Per-lane LDSM row base: lane l -> matrix l/8, row l%8
    //   rowoff = ((l>>4)<<3) + (l&7), half-sel = ((l>>3)&1)*16B
    const uint32_t lrow = (uint32_t)((bn + ((lane >> 4) << 3) + (lane & 7)) * (BT_STRIDE * 4))
                        + (uint32_t)(((lane >> 3) & 1) * 16);

    auto compute_chunk = [&](int buf) {
        const uint32_t* A = As + buf * A_WORDS;
        const uint32_t lbase = bt_u32 + (uint32_t)buf * BT_WORDS * 4 + lrow;
        const int mtl = warp_m * 2;

        uint32_t bw[2][16];
        uint4    aw[2][2];
        auto load_b = [&](uint32_t* d, int kk) {
            #pragma unroll
            for (int p = 0; p < 4; p++)
                ldsm4(d[4 * p], d[4 * p + 1], d[4 * p + 2], d[4 * p + 3],
                      lbase + (uint32_t)(p * 16 * BT_STRIDE * 4 + kk * 32));
        };
        auto load_a = [&](uint4* aa, int kk) {
            aa[0] = *reinterpret_cast<const uint4*>(&A[((mtl)     * 4 + kk) * 128 + lane * 4]);
            aa[1] = *reinterpret_cast<const uint4*>(&A[((mtl + 1) * 4 + kk) * 128 + lane * 4]);
        };

        load_b(bw[0], 0);
        load_a(aw[0], 0);
        #pragma unroll
        for (int kk = 0; kk < 4; kk++) {
            if (kk < 3) {
                load_b(bw[(kk + 1) & 1], kk + 1);
                load_a(aw[(kk + 1) & 1], kk + 1);
            }
            const uint32_t* cur = bw[kk & 1];
            const uint4* a = aw[kk & 1];
            #pragma unroll
            for (int p = 0; p < 4; p++) {
                mma_tf32(acc[0][2 * p],     a[0], cur[4 * p + 0], cur[4 * p + 1]);
                mma_tf32(acc[1][2 * p],     a[1], cur[4 * p + 0], cur[4 * p + 1]);
                mma_tf32(acc[0][2 * p + 1], a[0], cur[4 * p + 2], cur[4 * p + 3]);
                mma_tf32(acc[1][2 * p + 1], a[1], cur[4 * p + 2], cur[4 * p + 3]);
            }
        }
    };

    // Prologue: stage chunk 0.
    load_chunk(0, 0);
    asm volatile("cp.async.wait_group 0;\n");
    __syncthreads();

    #pragma unroll 1
    for (int c = 0; c < NCHUNK; c++) {
        const int buf = c & 1;
        if (c + 1 < NCHUNK) {
            load_chunk(buf ^ 1, c + 1);
            compute_chunk(buf);
            asm volatile("cp.async.wait_group 0;\n");
            __syncthreads();
        } else {
            compute_chunk(buf);
        }
    }

    // Epilogue: bias add + float2 stores.
    const int am = warp_m * 32;
    #pragma unroll
    for (int mi = 0; mi < 2; mi++) {
        const int mrow = m0 + am + mi * 16 + group;
        const float bv0 = Bv[mrow];
        const float bv1 = Bv[mrow + 8];
        #pragma unroll
        for (int ni = 0; ni < 8; ni++) {
            const int n = n0 + bn + ni * 8 + tig * 2;
            if (n < NSP) {
                float2 v0 = make_float2(acc[mi][ni][0] + bv0, acc[mi][ni][1] + bv0);
                *reinterpret_cast<float2*>(&O[(size_t)mrow * NSP + n]) = v0;
                float2 v1 = make_float2(acc[mi][ni][2] + bv1, acc[mi][ni][3] + bv1);
                *reinterpret_cast<float2*>(&O[(size_t)(mrow + 8) * NSP + n]) = v1;
            }
        }
    }
}

extern "C" void kernel_launch(void* const* d_in, const int* in_sizes, int n_in,
                              void* d_out, int out_size) {
    const float* x      = (const float*)d_in[0];
    const float* weight = (const float*)d_in[1];
    const float* bias   = (const float*)d_in[2];
    const int*   subj   = (const int*)d_in[3];
    float*       out    = (float*)d_out;

    // 1) weights -> tf32 fragment-ordered scratch
    wfrag_kernel<<<NSUBJ * CIN * CIN / 4 / 256, 256>>>(weight);

    // 2) main GEMM
    cudaFuncSetAttribute(subject_tf32_kernel,
                         cudaFuncAttributeMaxDynamicSharedMemorySize, SMEM_BYTES);
    dim3 block(256);
    dim3 grid((NSP + TN - 1) / TN, CIN / TM, 256);   // (24, 2, 256)
    subject_tf32_kernel<<<grid, block, SMEM_BYTES>>>(x, bias, subj, out);
}